// round 14
// baseline (speedup 1.0000x reference)
#include <cuda_runtime.h>
#include <math.h>

#define MAXBLK 1024

__device__ __align__(16) float g_Acoef[81 * 4];
__device__ __align__(16) float g_q[(1 << 17) * 4];
__device__ __align__(16) float g_part[MAXBLK * 8];
__device__ int g_ticket;                 // monotonic across launches
__device__ volatile int g_acoef_flag;    // released as gen+1 (by block 0 only)

__device__ __forceinline__ float pick_phase(int ph, float hr, float hi)
{
    return (ph == 0) ? hr : (ph == 1) ? -hi : (ph == 2) ? -hr : hi;
}

// ---------------------------------------------------------------------------
// Main kernel: setup(block 0, lane-parallel) + warp-autonomous pooling
// (single buffer, 1-deep prefetch) + circuit + per-block partials.
// One tile (256 items) per block. 3 blocks/SM -> 24 warps.
// The only spin is on block 0's flag: forward-progress safe at any grid size.
// ---------------------------------------------------------------------------
__global__ __launch_bounds__(256, 3)
void main_kernel(const float* __restrict__ x,
                 const float* __restrict__ W,
                 int B, int nb)
{
    __shared__ float2 wbuf[8][288];       // per-warp buffer, 18,432 B
    __shared__ float4 As[81];
    __shared__ float wsum[8][8];
    __shared__ int shGen;
    __shared__ struct {
        float CS[24][2];
        float Mre[16][16];
        float Mim[16][16];
        float G[4][16][16];
    } su;

    int tid = threadIdx.x;
    int lane = tid & 31;
    int w = tid >> 5;

    if (tid == 0) shGen = atomicAdd(&g_ticket, 1) / nb;
    __syncthreads();
    int gen = shGen;

    // ---- Block 0: build the 4x81 coefficient table ----
    if (blockIdx.x == 0) {
        if (tid < 24) {
            float c, s;
            __sincosf(W[tid] * 0.5f, &s, &c);
            su.CS[tid][0] = c;
            su.CS[tid][1] = s;
        }
        __syncthreads();
        {
            int i = lane & 15;
            int jl = lane >> 4;
            int j = w * 2 + jl;
            float re = (i == j) ? 1.f : 0.f;
            float im = 0.f;
#pragma unroll
            for (int l = 0; l < 2; l++) {
#pragma unroll
                for (int g2 = 0; g2 < 4; g2++) {
                    int gi = (l * 4 + g2) * 3;
                    const int m = 1 << (3 - g2);
                    float c, s, pre, pim;
                    c = su.CS[gi + 0][0]; s = su.CS[gi + 0][1];
                    pre = __shfl_xor_sync(0xffffffffu, re, m);
                    pim = __shfl_xor_sync(0xffffffffu, im, m);
                    {
                        float nr = fmaf(s, pim, c * re);
                        float ni = fmaf(-s, pre, c * im);
                        re = nr; im = ni;
                    }
                    c = su.CS[gi + 1][0]; s = su.CS[gi + 1][1];
                    pre = __shfl_xor_sync(0xffffffffu, re, m);
                    pim = __shfl_xor_sync(0xffffffffu, im, m);
                    {
                        float sg = (i & m) ? s : -s;
                        float nr = fmaf(sg, pre, c * re);
                        float ni = fmaf(sg, pim, c * im);
                        re = nr; im = ni;
                    }
                    c = su.CS[gi + 2][0]; s = su.CS[gi + 2][1];
                    {
                        float tt = (i & m) ? -s : s;
                        float nr = fmaf(tt, im, c * re);
                        float ni = fmaf(-tt, re, c * im);
                        re = nr; im = ni;
                    }
                }
#pragma unroll
                for (int g2 = 0; g2 < 4; g2++) {
                    int t2 = (g2 + 1) & 3;
                    int cm = 1 << (3 - g2), tm = 1 << (3 - t2);
                    int src = (((i & cm) ? (i ^ tm) : i) | (jl << 4));
                    re = __shfl_sync(0xffffffffu, re, src);
                    im = __shfl_sync(0xffffffffu, im, src);
                }
            }
            su.Mre[i][j] = re;
            su.Mim[i][j] = im;
        }
        __syncthreads();
        {
            int j2 = tid >> 4, k2 = tid & 15;
            float hr0 = 0, hr1 = 0, hr2 = 0, hr3 = 0;
            float hi0 = 0, hi1 = 0, hi2 = 0, hi3 = 0;
#pragma unroll
            for (int i2 = 0; i2 < 16; i2++) {
                float ar = su.Mre[i2][j2], ai = su.Mim[i2][j2];
                float br = su.Mre[i2][k2], bi = su.Mim[i2][k2];
                float tr = ar * br + ai * bi;
                float ti = ar * bi - ai * br;
                if (i2 & 8) { hr0 -= tr; hi0 -= ti; } else { hr0 += tr; hi0 += ti; }
                if (i2 & 4) { hr1 -= tr; hi1 -= ti; } else { hr1 += tr; hi1 += ti; }
                if (i2 & 2) { hr2 -= tr; hi2 -= ti; } else { hr2 += tr; hi2 += ti; }
                if (i2 & 1) { hr3 -= tr; hi3 -= ti; } else { hr3 += tr; hi3 += ti; }
            }
            int ph = (__popc(j2) - __popc(k2)) & 3;
            su.G[0][j2][k2] = pick_phase(ph, hr0, hi0);
            su.G[1][j2][k2] = pick_phase(ph, hr1, hi1);
            su.G[2][j2][k2] = pick_phase(ph, hr2, hi2);
            su.G[3][j2][k2] = pick_phase(ph, hr3, hi3);
        }
        __syncthreads();
        for (int idx = tid; idx < 324; idx += 256) {
            int ow = idx / 81;
            int m = idx % 81;
            int md[4] = { m / 27, (m / 9) % 3, (m / 3) % 3, m % 3 };
            float acc = 0.f;
#pragma unroll
            for (int t = 0; t < 16; t++) {
                int jj = 0, kk = 0;
                float sgn = 1.f;
#pragma unroll
                for (int w2 = 0; w2 < 4; w2++) {
                    int tb = (t >> (3 - w2)) & 1;
                    int jb, kb;
                    if (md[w2] == 2) { jb = tb; kb = 1 - tb; }
                    else { jb = tb; kb = tb; if (md[w2] == 1 && tb == 1) sgn = -sgn; }
                    jj |= jb << (3 - w2);
                    kk |= kb << (3 - w2);
                }
                acc += sgn * su.G[ow][jj][kk];
            }
            g_Acoef[m * 4 + ow] = acc * (1.f / 16.f);
        }
        __threadfence();
        __syncthreads();
        if (tid == 0) g_acoef_flag = gen + 1;
    }

    // ---- Warp-autonomous pooling: one tile, 4 chunks, 1-deep prefetch ----
    const float4* x4 = (const float4*)x;
    long totalF4 = (long)B * 36;
    int rdBase = (lane >> 2) * 36 + (lane & 3) * 9;
    int myT = lane >> 3;
    int srcLane = (lane & 7) * 4;

    long base = (long)blockIdx.x * 9216 + (long)w * 1152;
    float A0 = 0.f, A1 = 0.f, A2 = 0.f, A3 = 0.f;
    float sx[9], sz[9];

    // prologue: chunk 0
#pragma unroll
    for (int k = 0; k < 9; k++) {
        long gi = base + lane + k * 32;
        float4 v = make_float4(0.f, 0.f, 0.f, 0.f);
        if (gi < totalF4) v = x4[gi];
        sx[k] = v.x + v.y;
        sz[k] = v.z + v.w;
    }

#pragma unroll
    for (int s = 0; s < 4; s++) {
        // store chunk s (consumes regs at issue)
#pragma unroll
        for (int k = 0; k < 9; k++)
            wbuf[w][lane + k * 32] = make_float2(sx[k], sz[k]);
        // prefetch chunk s+1 into the same regs (WAR-safe after STS issue)
        if (s < 3) {
            long nbase = base + (s + 1) * 288;
#pragma unroll
            for (int k = 0; k < 9; k++) {
                long gi = nbase + lane + k * 32;
                float4 v = make_float4(0.f, 0.f, 0.f, 0.f);
                if (gi < totalF4) v = x4[gi];
                sx[k] = v.x + v.y;
                sz[k] = v.z + v.w;
            }
        }
        __syncwarp();
        float r0 = 0.f, r1 = 0.f;
        const float2* tp = &wbuf[w][rdBase];
#pragma unroll
        for (int i = 0; i < 9; i++) {
            float2 v = tp[i];
            if (i % 3 == 0)      r0 += v.x + v.y;
            else if (i % 3 == 1) { r0 += v.x; r1 += v.y; }
            else                 r1 += v.x + v.y;
        }
        r0 += __shfl_xor_sync(0xffffffffu, r0, 1);
        r1 += __shfl_xor_sync(0xffffffffu, r1, 1);
        float r2 = __shfl_xor_sync(0xffffffffu, r0, 2);
        float r3 = __shfl_xor_sync(0xffffffffu, r1, 2);
        float b0 = __shfl_sync(0xffffffffu, r0, srcLane);
        float b1 = __shfl_sync(0xffffffffu, r1, srcLane);
        float b2 = __shfl_sync(0xffffffffu, r2, srcLane);
        float b3 = __shfl_sync(0xffffffffu, r3, srcLane);
        bool mine = (myT == s);
        A0 = mine ? b0 : A0;
        A1 = mine ? b1 : A1;
        A2 = mine ? b2 : A2;
        A3 = mine ? b3 : A3;
        // last shfl synchronized the warp; buffer reuse next iter is safe
    }

    // ---- Wait for coefficients (block 0's own flag only — deadlock-free) ----
    if (blockIdx.x != 0) {
        if (tid == 0) {
            while (g_acoef_flag < gen + 1) __nanosleep(32);
        }
        __syncthreads();
        __threadfence();
    }
    if (tid < 81) As[tid] = __ldcg(((const float4*)g_Acoef) + tid);
    __syncthreads();

    // ---- Circuit: lane's item is  blockIdx.x*256 + w*32 + lane ----
    int item = blockIdx.x * 256 + w * 32 + lane;
    float q0 = 0.f, q1 = 0.f, q2 = 0.f, q3 = 0.f;
    if (item < B) {
        const float inv = 1.f / 36.f;
        float c0, s0, c1, s1, c2, s2, c3, s3;
        __sincosf(A0 * inv, &s0, &c0);
        __sincosf(A1 * inv, &s1, &c1);
        __sincosf(A2 * inv, &s2, &c2);
        __sincosf(A3 * inv, &s3, &c3);
        float t01[9] = { 1.f, c1, s1, c0, c0 * c1, c0 * s1, s0, s0 * c1, s0 * s1 };
        float t23[9] = { 1.f, c3, s3, c2, c2 * c3, c2 * s3, s2, s2 * c3, s2 * s3 };
#pragma unroll
        for (int m = 0; m < 81; m++) {
            float bs = t01[m / 9] * t23[m % 9];
            float4 a = As[m];
            q0 = fmaf(a.x, bs, q0);
            q1 = fmaf(a.y, bs, q1);
            q2 = fmaf(a.z, bs, q2);
            q3 = fmaf(a.w, bs, q3);
        }
        ((float4*)g_q)[item] = make_float4(q0, q1, q2, q3);
    }

    // ---- Per-block partial sums ----
    float s8[8] = { q0, q1, q2, q3, q0 * q0, q1 * q1, q2 * q2, q3 * q3 };
#pragma unroll
    for (int sh = 16; sh; sh >>= 1)
#pragma unroll
        for (int k = 0; k < 8; k++) s8[k] += __shfl_xor_sync(0xffffffffu, s8[k], sh);
    if (lane == 0) {
#pragma unroll
        for (int k = 0; k < 8; k++) wsum[w][k] = s8[k];
    }
    __syncthreads();
    if (tid < 8) {
        float acc = 0.f;
#pragma unroll
        for (int ww = 0; ww < 8; ww++) acc += wsum[ww][tid];
        g_part[blockIdx.x * 8 + tid] = acc;
    }
}

// ---------------------------------------------------------------------------
// Norm: every block redundantly reduces the partials (L2-hot, deterministic),
// then normalizes its slice of q.
// ---------------------------------------------------------------------------
__global__ __launch_bounds__(256, 4)
void norm_kernel(const float* __restrict__ gamma,
                 const float* __restrict__ beta,
                 float* __restrict__ out,
                 int B, int nblocks)
{
    __shared__ double red[8][32];
    __shared__ double tot[8];
    __shared__ float nrm[8];

    int tid = threadIdx.x;
    int k = tid & 7;
    int slice = tid >> 3;
    double acc = 0.0;
    for (int b = slice; b < nblocks; b += 32)
        acc += (double)g_part[b * 8 + k];
    red[k][slice] = acc;
    __syncthreads();
    if (tid < 8) {
        double t = 0.0;
#pragma unroll
        for (int i = 0; i < 32; i++) t += red[tid][i];
        tot[tid] = t;
    }
    __syncthreads();
    if (tid < 4) {
        double mean = tot[tid] / (double)B;
        double var = tot[4 + tid] / (double)B - mean * mean;
        float scale = gamma[tid] * rsqrtf((float)var + 1e-5f);
        nrm[tid] = scale;
        nrm[4 + tid] = beta[tid] - (float)mean * scale;
    }
    __syncthreads();

    int item = blockIdx.x * 256 + tid;
    if (item < B) {
        float4 qv = ((const float4*)g_q)[item];
        float4 o;
        o.x = fmaf(qv.x, nrm[0], nrm[4]);
        o.y = fmaf(qv.y, nrm[1], nrm[5]);
        o.z = fmaf(qv.z, nrm[2], nrm[6]);
        o.w = fmaf(qv.w, nrm[3], nrm[7]);
        ((float4*)out)[item] = o;
    }
}

// ---------------------------------------------------------------------------
extern "C" void kernel_launch(void* const* d_in, const int* in_sizes, int n_in,
                              void* d_out, int out_size)
{
    const float* x     = (const float*)d_in[0];
    const float* W     = (const float*)d_in[1];
    const float* gamma = (const float*)d_in[2];
    const float* beta  = (const float*)d_in[3];
    float* out = (float*)d_out;

    int B = in_sizes[0] / 144;
    int nb = (B + 255) / 256;
    if (nb > MAXBLK) nb = MAXBLK;

    main_kernel<<<nb, 256>>>(x, W, B, nb);
    norm_kernel<<<nb, 256>>>(gamma, beta, out, B, nb);
}

// round 15
// speedup vs baseline: 1.3549x; 1.3549x over previous
#include <cuda_runtime.h>
#include <math.h>

#define MAXBLK 1024

__device__ __align__(16) float g_Acoef[81 * 4];
__device__ __align__(16) float g_q[(1 << 17) * 4];
__device__ __align__(16) float g_part[MAXBLK * 8];
__device__ int g_ticket;                 // monotonic across launches
__device__ volatile int g_acoef_flag;    // released as gen+1 (by block 0 only)

__device__ __forceinline__ float pick_phase(int ph, float hr, float hi)
{
    return (ph == 0) ? hr : (ph == 1) ? -hi : (ph == 2) ? -hr : hi;
}

// ---------------------------------------------------------------------------
// Main kernel: setup(block 0, lane-parallel) + warp-autonomous pooling
// (single buffer, 1-deep prefetch) + circuit + per-block partials.
// One tile (256 items) per block. 3 blocks/SM -> 24 warps.
// ---------------------------------------------------------------------------
__global__ __launch_bounds__(256, 3)
void main_kernel(const float* __restrict__ x,
                 const float* __restrict__ W,
                 int B, int nb)
{
    __shared__ float2 wbuf[8][288];       // per-warp buffer, 18,432 B
    __shared__ float4 As[81];
    __shared__ float wsum[8][8];
    __shared__ int shGen;
    __shared__ struct {
        float CS[24][2];
        float Mre[16][16];
        float Mim[16][16];
        float G[4][16][16];
    } su;

    int tid = threadIdx.x;
    int lane = tid & 31;
    int w = tid >> 5;

    if (tid == 0) shGen = atomicAdd(&g_ticket, 1) / nb;
    __syncthreads();
    int gen = shGen;

    // ---- Block 0: build the 4x81 coefficient table ----
    if (blockIdx.x == 0) {
        if (tid < 24) {
            float c, s;
            __sincosf(W[tid] * 0.5f, &s, &c);
            su.CS[tid][0] = c;
            su.CS[tid][1] = s;
        }
        __syncthreads();
        {
            int i = lane & 15;
            int jl = lane >> 4;
            int j = w * 2 + jl;
            float re = (i == j) ? 1.f : 0.f;
            float im = 0.f;
#pragma unroll
            for (int l = 0; l < 2; l++) {
#pragma unroll
                for (int g2 = 0; g2 < 4; g2++) {
                    int gi = (l * 4 + g2) * 3;
                    const int m = 1 << (3 - g2);
                    float c, s, pre, pim;
                    c = su.CS[gi + 0][0]; s = su.CS[gi + 0][1];
                    pre = __shfl_xor_sync(0xffffffffu, re, m);
                    pim = __shfl_xor_sync(0xffffffffu, im, m);
                    {
                        float nr = fmaf(s, pim, c * re);
                        float ni = fmaf(-s, pre, c * im);
                        re = nr; im = ni;
                    }
                    c = su.CS[gi + 1][0]; s = su.CS[gi + 1][1];
                    pre = __shfl_xor_sync(0xffffffffu, re, m);
                    pim = __shfl_xor_sync(0xffffffffu, im, m);
                    {
                        float sg = (i & m) ? s : -s;
                        float nr = fmaf(sg, pre, c * re);
                        float ni = fmaf(sg, pim, c * im);
                        re = nr; im = ni;
                    }
                    c = su.CS[gi + 2][0]; s = su.CS[gi + 2][1];
                    {
                        float tt = (i & m) ? -s : s;
                        float nr = fmaf(tt, im, c * re);
                        float ni = fmaf(-tt, re, c * im);
                        re = nr; im = ni;
                    }
                }
#pragma unroll
                for (int g2 = 0; g2 < 4; g2++) {
                    int t2 = (g2 + 1) & 3;
                    int cm = 1 << (3 - g2), tm = 1 << (3 - t2);
                    int src = (((i & cm) ? (i ^ tm) : i) | (jl << 4));
                    re = __shfl_sync(0xffffffffu, re, src);
                    im = __shfl_sync(0xffffffffu, im, src);
                }
            }
            su.Mre[i][j] = re;
            su.Mim[i][j] = im;
        }
        __syncthreads();
        {
            int j2 = tid >> 4, k2 = tid & 15;
            float hr0 = 0, hr1 = 0, hr2 = 0, hr3 = 0;
            float hi0 = 0, hi1 = 0, hi2 = 0, hi3 = 0;
#pragma unroll
            for (int i2 = 0; i2 < 16; i2++) {
                float ar = su.Mre[i2][j2], ai = su.Mim[i2][j2];
                float br = su.Mre[i2][k2], bi = su.Mim[i2][k2];
                float tr = ar * br + ai * bi;
                float ti = ar * bi - ai * br;
                if (i2 & 8) { hr0 -= tr; hi0 -= ti; } else { hr0 += tr; hi0 += ti; }
                if (i2 & 4) { hr1 -= tr; hi1 -= ti; } else { hr1 += tr; hi1 += ti; }
                if (i2 & 2) { hr2 -= tr; hi2 -= ti; } else { hr2 += tr; hi2 += ti; }
                if (i2 & 1) { hr3 -= tr; hi3 -= ti; } else { hr3 += tr; hi3 += ti; }
            }
            int ph = (__popc(j2) - __popc(k2)) & 3;
            su.G[0][j2][k2] = pick_phase(ph, hr0, hi0);
            su.G[1][j2][k2] = pick_phase(ph, hr1, hi1);
            su.G[2][j2][k2] = pick_phase(ph, hr2, hi2);
            su.G[3][j2][k2] = pick_phase(ph, hr3, hi3);
        }
        __syncthreads();
        for (int idx = tid; idx < 324; idx += 256) {
            int ow = idx / 81;
            int m = idx % 81;
            int md[4] = { m / 27, (m / 9) % 3, (m / 3) % 3, m % 3 };
            float acc = 0.f;
#pragma unroll
            for (int t = 0; t < 16; t++) {
                int jj = 0, kk = 0;
                float sgn = 1.f;
#pragma unroll
                for (int w2 = 0; w2 < 4; w2++) {
                    int tb = (t >> (3 - w2)) & 1;
                    int jb, kb;
                    if (md[w2] == 2) { jb = tb; kb = 1 - tb; }
                    else { jb = tb; kb = tb; if (md[w2] == 1 && tb == 1) sgn = -sgn; }
                    jj |= jb << (3 - w2);
                    kk |= kb << (3 - w2);
                }
                acc += sgn * su.G[ow][jj][kk];
            }
            g_Acoef[m * 4 + ow] = acc * (1.f / 16.f);
        }
        __threadfence();
        __syncthreads();
        if (tid == 0) g_acoef_flag = gen + 1;
    }

    // ---- Warp-autonomous pooling: one tile, 4 chunks, 1-deep prefetch ----
    const float4* x4 = (const float4*)x;
    long totalF4 = (long)B * 36;
    int rdBase = (lane >> 2) * 36 + (lane & 3) * 9;
    int myT = lane >> 3;
    int srcLane = (lane & 7) * 4;

    long base = (long)blockIdx.x * 9216 + (long)w * 1152;
    float A0 = 0.f, A1 = 0.f, A2 = 0.f, A3 = 0.f;
    float sx[9], sz[9];

    // prologue: chunk 0
#pragma unroll
    for (int k = 0; k < 9; k++) {
        long gi = base + lane + k * 32;
        float4 v = make_float4(0.f, 0.f, 0.f, 0.f);
        if (gi < totalF4) v = x4[gi];
        sx[k] = v.x + v.y;
        sz[k] = v.z + v.w;
    }

#pragma unroll
    for (int s = 0; s < 4; s++) {
#pragma unroll
        for (int k = 0; k < 9; k++)
            wbuf[w][lane + k * 32] = make_float2(sx[k], sz[k]);
        if (s < 3) {
            long nbase = base + (s + 1) * 288;
#pragma unroll
            for (int k = 0; k < 9; k++) {
                long gi = nbase + lane + k * 32;
                float4 v = make_float4(0.f, 0.f, 0.f, 0.f);
                if (gi < totalF4) v = x4[gi];
                sx[k] = v.x + v.y;
                sz[k] = v.z + v.w;
            }
        }
        __syncwarp();
        float r0 = 0.f, r1 = 0.f;
        const float2* tp = &wbuf[w][rdBase];
#pragma unroll
        for (int i = 0; i < 9; i++) {
            float2 v = tp[i];
            if (i % 3 == 0)      r0 += v.x + v.y;
            else if (i % 3 == 1) { r0 += v.x; r1 += v.y; }
            else                 r1 += v.x + v.y;
        }
        r0 += __shfl_xor_sync(0xffffffffu, r0, 1);
        r1 += __shfl_xor_sync(0xffffffffu, r1, 1);
        float r2 = __shfl_xor_sync(0xffffffffu, r0, 2);
        float r3 = __shfl_xor_sync(0xffffffffu, r1, 2);
        float b0 = __shfl_sync(0xffffffffu, r0, srcLane);
        float b1 = __shfl_sync(0xffffffffu, r1, srcLane);
        float b2 = __shfl_sync(0xffffffffu, r2, srcLane);
        float b3 = __shfl_sync(0xffffffffu, r3, srcLane);
        bool mine = (myT == s);
        A0 = mine ? b0 : A0;
        A1 = mine ? b1 : A1;
        A2 = mine ? b2 : A2;
        A3 = mine ? b3 : A3;
    }

    // ---- Wait for coefficients (block 0's own flag only — deadlock-free) ----
    if (blockIdx.x != 0) {
        if (tid == 0) {
            while (g_acoef_flag < gen + 1) __nanosleep(32);
        }
        __syncthreads();
        __threadfence();
    }
    if (tid < 81) As[tid] = __ldcg(((const float4*)g_Acoef) + tid);
    __syncthreads();

    // ---- Circuit: lane's item is  blockIdx.x*256 + w*32 + lane ----
    int item = blockIdx.x * 256 + w * 32 + lane;
    float q0 = 0.f, q1 = 0.f, q2 = 0.f, q3 = 0.f;
    if (item < B) {
        const float inv = 1.f / 36.f;
        float c0, s0, c1, s1, c2, s2, c3, s3;
        __sincosf(A0 * inv, &s0, &c0);
        __sincosf(A1 * inv, &s1, &c1);
        __sincosf(A2 * inv, &s2, &c2);
        __sincosf(A3 * inv, &s3, &c3);
        float t01[9] = { 1.f, c1, s1, c0, c0 * c1, c0 * s1, s0, s0 * c1, s0 * s1 };
        float t23[9] = { 1.f, c3, s3, c2, c2 * c3, c2 * s3, s2, s2 * c3, s2 * s3 };
#pragma unroll
        for (int m = 0; m < 81; m++) {
            float bs = t01[m / 9] * t23[m % 9];
            float4 a = As[m];
            q0 = fmaf(a.x, bs, q0);
            q1 = fmaf(a.y, bs, q1);
            q2 = fmaf(a.z, bs, q2);
            q3 = fmaf(a.w, bs, q3);
        }
        ((float4*)g_q)[item] = make_float4(q0, q1, q2, q3);
    }

    // ---- Per-block partial sums ----
    float s8[8] = { q0, q1, q2, q3, q0 * q0, q1 * q1, q2 * q2, q3 * q3 };
#pragma unroll
    for (int sh = 16; sh; sh >>= 1)
#pragma unroll
        for (int k = 0; k < 8; k++) s8[k] += __shfl_xor_sync(0xffffffffu, s8[k], sh);
    if (lane == 0) {
#pragma unroll
        for (int k = 0; k < 8; k++) wsum[w][k] = s8[k];
    }
    __syncthreads();
    if (tid < 8) {
        float acc = 0.f;
#pragma unroll
        for (int ww = 0; ww < 8; ww++) acc += wsum[ww][tid];
        g_part[blockIdx.x * 8 + tid] = acc;
    }
}

// ---------------------------------------------------------------------------
// Norm: every block redundantly reduces the partials in FLOAT (FP64 only in
// the 4-thread epilogue), then normalizes its slice of q.
// ---------------------------------------------------------------------------
__global__ __launch_bounds__(256, 4)
void norm_kernel(const float* __restrict__ gamma,
                 const float* __restrict__ beta,
                 float* __restrict__ out,
                 int B, int nblocks)
{
    __shared__ float red[8][32];
    __shared__ float tot[8];
    __shared__ float nrm[8];

    int tid = threadIdx.x;
    int k = tid & 7;
    int slice = tid >> 3;
    float acc = 0.f;
    for (int b = slice; b < nblocks; b += 32)
        acc += g_part[b * 8 + k];
    red[k][slice] = acc;
    __syncthreads();
    if (tid < 8) {
        float t = 0.f;
#pragma unroll
        for (int i = 0; i < 32; i++) t += red[tid][i];
        tot[tid] = t;
    }
    __syncthreads();
    if (tid < 4) {
        // FP64 only here: 4 threads, a handful of ops.
        double mean = (double)tot[tid] / (double)B;
        double var = (double)tot[4 + tid] / (double)B - mean * mean;
        float scale = gamma[tid] * rsqrtf((float)var + 1e-5f);
        nrm[tid] = scale;
        nrm[4 + tid] = beta[tid] - (float)mean * scale;
    }
    __syncthreads();

    int item = blockIdx.x * 256 + tid;
    if (item < B) {
        float4 qv = ((const float4*)g_q)[item];
        float4 o;
        o.x = fmaf(qv.x, nrm[0], nrm[4]);
        o.y = fmaf(qv.y, nrm[1], nrm[5]);
        o.z = fmaf(qv.z, nrm[2], nrm[6]);
        o.w = fmaf(qv.w, nrm[3], nrm[7]);
        ((float4*)out)[item] = o;
    }
}

// ---------------------------------------------------------------------------
extern "C" void kernel_launch(void* const* d_in, const int* in_sizes, int n_in,
                              void* d_out, int out_size)
{
    const float* x     = (const float*)d_in[0];
    const float* W     = (const float*)d_in[1];
    const float* gamma = (const float*)d_in[2];
    const float* beta  = (const float*)d_in[3];
    float* out = (float*)d_out;

    int B = in_sizes[0] / 144;
    int nb = (B + 255) / 256;
    if (nb > MAXBLK) nb = MAXBLK;

    main_kernel<<<nb, 256>>>(x, W, B, nb);
    norm_kernel<<<nb, 256>>>(gamma, beta, out, B, nb);
}